// round 15
// baseline (speedup 1.0000x reference)
#include <cuda_runtime.h>
#include <math.h>

#define MAXM 32
#define PI_180 0.017453292519943295f
#define LN2F   0.6931471805599453f
#define MAXPART 8192
#define MAXCAND 524288

__device__ float g_pc[MAXPART];          // per-A-block neg-cls partials
__device__ float g_bc[8];                // per-image pos-cls accum (B)
__device__ float g_br[8];                // per-image reg accum (B)
__device__ float g_bn[8];                // per-image npos accum (B)
__device__ unsigned int g_cand_cnt = 0;  // candidate count (C resets)
__device__ unsigned int g_cand[MAXCAND];

struct F2 { float x, y; };

template<int AXIS, int SGN>
__device__ __forceinline__ int clip_axis(const F2* in, int n, float C, F2* out) {
    int m = 0;
    for (int i = 0; i < 8; i++) {
        if (i >= n) break;
        F2 cur = in[i];
        F2 nxt = in[(i + 1 == n) ? 0 : i + 1];
        float sc = (AXIS == 0) ? (cur.x - C) : (cur.y - C);
        float sn = (AXIS == 0) ? (nxt.x - C) : (nxt.y - C);
        if (SGN < 0) { sc = -sc; sn = -sn; }
        bool inc = (sc >= 0.f), inn = (sn >= 0.f);
        if (inc && m < 8) out[m++] = cur;
        if ((inc != inn) && m < 8) {
            float den = sc - sn;
            float t = sc / ((den == 0.f) ? 1.f : den);
            out[m].x = cur.x + t * (nxt.x - cur.x);
            out[m].y = cur.y + t * (nxt.y - cur.y);
            m++;
        }
    }
    return m;
}

__device__ float quad_rect_iou(const F2 q1[4],
                               float x1, float y1, float x2, float y2) {
    F2 pa[8], pb[8];
#pragma unroll
    for (int i = 0; i < 4; i++) pa[i] = q1[i];
    int n = 4;
    n = clip_axis<1, +1>(pa, n, y1, pb);
    n = clip_axis<0, -1>(pb, n, x2, pa);
    n = clip_axis<1, -1>(pa, n, y2, pb);
    n = clip_axis<0, +1>(pb, n, x1, pa);

    float s = 0.f;
    for (int i = 0; i < 8; i++) {
        if (i >= n) break;
        int j = (i + 1 == n) ? 0 : i + 1;
        s += pa[i].x * pa[j].y - pa[i].y * pa[j].x;
    }
    float inter = 0.5f * fabsf(s);

    float sa1 = 0.f;
#pragma unroll
    for (int i = 0; i < 4; i++) {
        int j = (i + 1) & 3;
        sa1 += q1[i].x * q1[j].y - q1[i].y * q1[j].x;
    }
    float a1 = fabsf(0.5f * sa1);
    float a2 = (x2 - x1) * (y2 - y1);
    return inter / fmaxf(a1 + a2 - inter, 1e-8f);
}

// ================= Kernel A: lean scan + neg focal + candidate emit ========
template<int M_T, int NC_T>
__global__ void __launch_bounds__(256)
scan_kernel(const float* __restrict__ cls,
            const float* __restrict__ anch,
            const float* __restrict__ ann,
            int A, int NC_rt, int M_rt)
{
    const int M  = M_T  ? M_T  : M_rt;
    const int NC = NC_T ? NC_T : NC_rt;
    const int b  = blockIdx.y;

    __shared__ float4 s_box[MAXM];
    __shared__ float  s_a04[MAXM];
    __shared__ float  s_cls[8 * 480];
    __shared__ float  s_anch[8 * 160];

    // zero per-image B-accumulators once per image per replay
    if (blockIdx.x == 0 && threadIdx.x == 0) {
        g_bc[b] = 0.f; g_br[b] = 0.f; g_bn[b] = 0.f;
    }

    // GT hbb prologue (spread: lanes 0,8,16,24 of each warp)
    if ((threadIdx.x & 7) == 0) {
        for (int j = (threadIdx.x >> 3); j < M; j += 32) {
            const float* ar = ann + ((size_t)b * M + j) * 6;
            float a0 = ar[0], a1 = ar[1], a2 = ar[2], a3 = ar[3], a4 = ar[4], a5 = ar[5];
            float t = a4 * PI_180;
            float sa = __sinf(t) * 0.5f;
            float cb = __cosf(t) * 0.5f;
            float p0x = a0 - sa * a3 - cb * a2;
            float p0y = a1 + cb * a3 - sa * a2;
            float p1x = a0 + sa * a3 - cb * a2;
            float p1y = a1 - cb * a3 - sa * a2;
            float p2x = 2.f * a0 - p0x;
            float p2y = 2.f * a1 - p0y;
            float p3x = 2.f * a0 - p1x;
            float p3y = 2.f * a1 - p1y;
            bool valid = (a5 != -1.0f);
            float hx1 = fminf(fminf(p0x, p1x), fminf(p2x, p3x));
            float hx2 = fmaxf(fmaxf(p0x, p1x), fmaxf(p2x, p3x));
            float hy1 = fminf(fminf(p0y, p1y), fminf(p2y, p3y));
            float hy2 = fmaxf(fmaxf(p0y, p1y), fmaxf(p2y, p3y));
            if (!valid) { hx1 = hx2 = hy1 = hy2 = 1e8f; }
            s_box[j] = make_float4(hx1, hy1, hx2, hy2);
            s_a04[j] = 0.4f * (hx2 - hx1) * (hy2 - hy1);
        }
    }

    const int a    = blockIdx.x * blockDim.x + threadIdx.x;
    const int warp = threadIdx.x >> 5;
    const int lane = threadIdx.x & 31;

    // per-warp staging: cls rows + anchor rows
    {
        int a0 = (blockIdx.x * blockDim.x) + (warp << 5);
        if (a0 < A) {
            if (NC_T != 0) {
                size_t base = ((size_t)b * A + a0) * (size_t)NC;
                int maxf = (A - a0) * NC;
                if (maxf > 32 * NC) maxf = 32 * NC;
                float* dstw = s_cls + warp * 480;
                if (maxf == 32 * NC && ((base & 3) == 0)) {
                    const float4* src4 = (const float4*)(cls + base);
                    float4* dst4 = (float4*)dstw;
#pragma unroll
                    for (int i = 0; i < 4; i++) {
                        int idx = lane + i * 32;
                        if (idx < 8 * NC) dst4[idx] = src4[idx];
                    }
                } else {
                    const float* src = cls + base;
                    for (int idx = lane; idx < maxf; idx += 32) dstw[idx] = src[idx];
                }
            }
            size_t abase = (size_t)a0 * 5;
            int maxa = (A - a0) * 5;
            if (maxa > 160) maxa = 160;
            float* dsta = s_anch + warp * 160;
            if (maxa == 160 && ((abase & 3) == 0)) {
                const float4* src4 = (const float4*)(anch + abase);
                float4* dst4 = (float4*)dsta;
#pragma unroll
                for (int i = 0; i < 2; i++) {
                    int idx = lane + i * 32;
                    if (idx < 40) dst4[idx] = src4[idx];
                }
            } else {
                const float* src = anch + abase;
                for (int idx = lane; idx < maxa; idx += 32) dsta[idx] = src[idx];
            }
        }
    }
    __syncthreads();

    // phase 1: 0.4-threshold scan (single max chain)
    const float* arow = s_anch + warp * 160 + lane * 5;
    float ax1 = arow[0], ay1 = arow[1], ax2 = arow[2], ay2 = arow[3];
    float c04 = 0.4f * (ax2 - ax1) * (ay2 - ay1);

    float mx = -3.0e38f;
#pragma unroll 4
    for (int j = 0; j < M; j++) {
        float4 bb = s_box[j];
        float iw = fmaxf(fminf(ax2, bb.z) - fmaxf(ax1, bb.x), 0.f);
        float ih = fmaxf(fminf(ay2, bb.w) - fmaxf(ay1, bb.y), 0.f);
        mx = fmaxf(mx, fmaf(1.4f, iw * ih, -s_a04[j]));
    }

    bool act  = (a < A);
    bool cand = act && (mx >= c04);
    bool neg  = act && !cand;

    // emit candidates (warp-aggregated global atomic)
    {
        unsigned bal = __ballot_sync(0xffffffffu, cand);
        int cw = __popc(bal);
        unsigned base = 0;
        if (lane == 0 && cw) base = atomicAdd(&g_cand_cnt, (unsigned)cw);
        base = __shfl_sync(0xffffffffu, base, 0);
        if (cand) {
            unsigned slot = base + __popc(bal & ((1u << lane) - 1u));
            if (slot < MAXCAND)
                g_cand[slot] = ((unsigned)b << 20) | (unsigned)a;
        }
    }

    // neg focal loss
    float acc = 0.f;
    if (neg) {
        const float* crow = (NC_T != 0) ? (s_cls + warp * 480 + lane * NC)
                                        : (cls + ((size_t)b * A + (size_t)a) * NC);
#pragma unroll
        for (int k = 0; k < (NC_T ? NC_T : 32); k++) {
            if (NC_T == 0 && k >= NC) break;
            float p = fminf(fmaxf(crow[k], 1e-4f), 1.f - 1e-4f);
            acc = fmaf(p * p, __log2f(1.f - p), acc);
        }
    }
    float closs = acc * (-0.75f * LN2F);

    // block reduction of closs
#pragma unroll
    for (int o = 16; o > 0; o >>= 1)
        closs += __shfl_down_sync(0xffffffffu, closs, o);
    __shared__ float red_c[8];
    if (lane == 0) red_c[warp] = closs;
    __syncthreads();
    if (threadIdx.x == 0) {
        float tc = 0.f;
#pragma unroll
        for (int w = 0; w < 8; w++) tc += red_c[w];
        g_pc[b * gridDim.x + blockIdx.x] = tc;
    }
}

// ================= Kernel B: candidate processing ===========================
template<int M_T, int NC_T>
__global__ void __launch_bounds__(256)
cand_kernel(const float* __restrict__ cls,
            const float* __restrict__ reg,
            const float* __restrict__ anch,
            const float* __restrict__ ann,
            int A, int NC_rt, int M_rt, int B)
{
    const int M  = M_T  ? M_T  : M_rt;
    const int NC = NC_T ? NC_T : NC_rt;

    __shared__ float4 s_box[8][MAXM];
    __shared__ float  s_area[8][MAXM];
    __shared__ float  s_gpx[8][MAXM][4];
    __shared__ float  s_gpy[8][MAXM][4];
    __shared__ float  s_ann[8][MAXM][6];
    __shared__ float  s_ac[8], s_ar[8], s_an[8];

    if (threadIdx.x < 8) {
        s_ac[threadIdx.x] = 0.f; s_ar[threadIdx.x] = 0.f; s_an[threadIdx.x] = 0.f;
    }
    // prologue: all (image, box) pairs
    for (int t = threadIdx.x; t < B * M; t += blockDim.x) {
        int img = t / M, j = t % M;
        const float* ar = ann + ((size_t)img * M + j) * 6;
        float a0 = ar[0], a1 = ar[1], a2 = ar[2], a3 = ar[3], a4 = ar[4], a5 = ar[5];
        s_ann[img][j][0] = a0; s_ann[img][j][1] = a1; s_ann[img][j][2] = a2;
        s_ann[img][j][3] = a3; s_ann[img][j][4] = a4; s_ann[img][j][5] = a5;
        float tt = a4 * PI_180;
        float sa = __sinf(tt) * 0.5f;
        float cb = __cosf(tt) * 0.5f;
        float p0x = a0 - sa * a3 - cb * a2;
        float p0y = a1 + cb * a3 - sa * a2;
        float p1x = a0 + sa * a3 - cb * a2;
        float p1y = a1 - cb * a3 - sa * a2;
        float p2x = 2.f * a0 - p0x;
        float p2y = 2.f * a1 - p0y;
        float p3x = 2.f * a0 - p1x;
        float p3y = 2.f * a1 - p1y;
        s_gpx[img][j][0] = p0x; s_gpx[img][j][1] = p1x;
        s_gpx[img][j][2] = p2x; s_gpx[img][j][3] = p3x;
        s_gpy[img][j][0] = p0y; s_gpy[img][j][1] = p1y;
        s_gpy[img][j][2] = p2y; s_gpy[img][j][3] = p3y;
        bool valid = (a5 != -1.0f);
        float hx1 = fminf(fminf(p0x, p1x), fminf(p2x, p3x));
        float hx2 = fmaxf(fmaxf(p0x, p1x), fmaxf(p2x, p3x));
        float hy1 = fminf(fminf(p0y, p1y), fminf(p2y, p3y));
        float hy2 = fmaxf(fmaxf(p0y, p1y), fmaxf(p2y, p3y));
        if (!valid) { hx1 = hx2 = hy1 = hy2 = 1e8f; }
        s_box[img][j]  = make_float4(hx1, hy1, hx2, hy2);
        s_area[img][j] = (hx2 - hx1) * (hy2 - hy1);
    }
    __syncthreads();

    unsigned cnt = g_cand_cnt;
    if (cnt > MAXCAND) cnt = MAXCAND;

    for (unsigned i = blockIdx.x * blockDim.x + threadIdx.x; i < cnt;
         i += gridDim.x * blockDim.x) {
        unsigned u = g_cand[i];
        int b = (int)(u >> 20);
        int a = (int)(u & 0xFFFFFu);

        const float* arow = anch + (size_t)a * 5;
        float ax1 = arow[0], ay1 = arow[1], ax2 = arow[2], ay2 = arow[3], ath = arow[4];
        float aw = ax2 - ax1, ah = ay2 - ay1;
        float aArea = aw * ah;

        // exact cross-mult argmax
        float cbi = -1.f, cbu = 1.f;
        int hg = 0;
#pragma unroll 8
        for (int j = 0; j < M; j++) {
            float4 bb = s_box[b][j];
            float iw = fmaxf(fminf(ax2, bb.z) - fmaxf(ax1, bb.x), 0.f);
            float ih = fmaxf(fminf(ay2, bb.w) - fmaxf(ay1, bb.y), 0.f);
            float inter = iw * ih;
            float ua = aArea + s_area[b][j] - inter;
            if (inter * cbu > cbi * ua) { cbi = inter; cbu = ua; hg = j; }
        }

        bool pos = false;
        if (cbi >= 0.6f * cbu) {   // hmax >= 0.6
            F2 q1[4];
#pragma unroll
            for (int c = 0; c < 4; c++) {
                q1[c].x = s_gpx[b][hg][c];
                q1[c].y = s_gpy[b][hg][c];
            }
            pos = (quad_rect_iou(q1, ax1, ay1, ax2, ay2) >= 0.3f);
        }

        if (pos) {
            // pos focal loss
            float acc = 0.f;
            const float* crow = cls + ((size_t)b * A + (size_t)a) * NC;
            int tc = (int)s_ann[b][hg][5];
#pragma unroll
            for (int k = 0; k < (NC_T ? NC_T : 32); k++) {
                if (NC_T == 0 && k >= NC) break;
                float p = fminf(fmaxf(crow[k], 1e-4f), 1.f - 1e-4f);
                if (k == tc) {
                    float q = 1.f - p;
                    acc = fmaf((1.f / 3.f) * q * q, __log2f(p), acc);
                } else {
                    acc = fmaf(p * p, __log2f(1.f - p), acc);
                }
            }
            float closs = acc * (-0.75f * LN2F);

            // regression smooth-L1
            float acx = ax1 + 0.5f * aw;
            float acy = ay1 + 0.5f * ah;
            float gw = fmaxf(s_ann[b][hg][2], 1.f);
            float gh = fmaxf(s_ann[b][hg][3], 1.f);
            float t5[5];
            t5[0] = ((s_ann[b][hg][0] - acx) / aw) * 10.f;
            t5[1] = ((s_ann[b][hg][1] - acy) / ah) * 10.f;
            t5[2] = __logf(gw / aw) * 5.f;
            t5[3] = __logf(gh / ah) * 5.f;
            t5[4] = ((s_ann[b][hg][4] - ath) * PI_180) * 10.f;
            const float* rrow = reg + ((size_t)b * A + (size_t)a) * 5;
            float rsum = 0.f;
#pragma unroll
            for (int k = 0; k < 5; k++) {
                float d = fabsf(t5[k] - rrow[k]);
                rsum += (d <= (1.f / 9.f)) ? 4.5f * d * d : (d - (0.5f / 9.f));
            }

            atomicAdd(&s_ac[b], closs);
            atomicAdd(&s_ar[b], rsum);
            atomicAdd(&s_an[b], 1.f);
        }
    }
    __syncthreads();
    if (threadIdx.x < 8) {
        int t = threadIdx.x;
        if (s_an[t] != 0.f || s_ac[t] != 0.f) {
            atomicAdd(&g_bc[t], s_ac[t]);
            atomicAdd(&g_br[t], s_ar[t]);
            atomicAdd(&g_bn[t], s_an[t]);
        }
    }
}

// ================= Kernel C: finalize =======================================
__global__ void finalize_kernel(float* __restrict__ out, int B, int nblk) {
    int w = threadIdx.x >> 5;
    int lane = threadIdx.x & 31;
    __shared__ float s_c[8], s_r[8];
    if (w < B) {
        float tc = 0.f;
        for (int i = lane; i < nblk; i += 32)
            tc += g_pc[w * nblk + i];
#pragma unroll
        for (int o = 16; o > 0; o >>= 1)
            tc += __shfl_down_sync(0xffffffffu, tc, o);
        if (lane == 0) {
            float np = g_bn[w];
            float cl = tc + g_bc[w];
            s_c[w] = cl / fmaxf(np, 1.f);
            s_r[w] = (np > 0.f) ? (g_br[w] / fmaxf(np * 5.f, 1.f)) : 0.f;
        }
    }
    __syncthreads();
    if (threadIdx.x == 0) {
        float cm = 0.f, rm = 0.f;
        for (int bb = 0; bb < B; bb++) { cm += s_c[bb]; rm += s_r[bb]; }
        out[0] = cm / (float)B;
        out[1] = rm / (float)B;
        g_cand_cnt = 0;   // reset for next graph replay
    }
}

extern "C" void kernel_launch(void* const* d_in, const int* in_sizes, int n_in,
                              void* d_out, int out_size) {
    const float* cls  = (const float*)d_in[0];
    const float* reg  = (const float*)d_in[1];
    const float* anch = (const float*)d_in[2];
    const float* ann  = (const float*)d_in[3];
    float* out = (float*)d_out;

    int A  = in_sizes[2] / 5;
    int B  = in_sizes[1] / (A * 5);
    int NC = in_sizes[0] / (B * A);
    int M  = in_sizes[3] / (B * 6);
    if (M > MAXM) M = MAXM;
    int Bc = (B > 8) ? 8 : B;   // B-kernel shared arrays sized for 8 images

    int nblk = (A + 255) / 256;
    dim3 gridA(nblk, Bc);
    if (M == 32 && NC == 15) {
        scan_kernel<32, 15><<<gridA, 256>>>(cls, anch, ann, A, NC, M);
        cand_kernel<32, 15><<<96, 256>>>(cls, reg, anch, ann, A, NC, M, Bc);
    } else {
        scan_kernel<0, 0><<<gridA, 256>>>(cls, anch, ann, A, NC, M);
        cand_kernel<0, 0><<<96, 256>>>(cls, reg, anch, ann, A, NC, M, Bc);
    }
    finalize_kernel<<<1, 256>>>(out, Bc, nblk);
}

// round 16
// speedup vs baseline: 1.3489x; 1.3489x over previous
#include <cuda_runtime.h>
#include <math.h>

#define MAXM 32
#define PI_180 0.017453292519943295f
#define LN2F   0.6931471805599453f
#define MAXPART 8192
#define MAXCAND 524288

__device__ float g_pc[MAXPART];          // per-scan-block neg-cls partials
__device__ float g_bc[8];                // per-image pos-cls accum
__device__ float g_br[8];                // per-image reg accum
__device__ float g_bn[8];                // per-image npos accum
__device__ unsigned int g_cand_cnt = 0;  // candidate count
__device__ unsigned int g_done2 = 0;     // cand_kernel completion counter
__device__ unsigned int g_cand[MAXCAND];

struct F2 { float x, y; };

template<int AXIS, int SGN>
__device__ __forceinline__ int clip_axis(const F2* in, int n, float C, F2* out) {
    int m = 0;
    for (int i = 0; i < 8; i++) {
        if (i >= n) break;
        F2 cur = in[i];
        F2 nxt = in[(i + 1 == n) ? 0 : i + 1];
        float sc = (AXIS == 0) ? (cur.x - C) : (cur.y - C);
        float sn = (AXIS == 0) ? (nxt.x - C) : (nxt.y - C);
        if (SGN < 0) { sc = -sc; sn = -sn; }
        bool inc = (sc >= 0.f), inn = (sn >= 0.f);
        if (inc && m < 8) out[m++] = cur;
        if ((inc != inn) && m < 8) {
            float den = sc - sn;
            float t = sc / ((den == 0.f) ? 1.f : den);
            out[m].x = cur.x + t * (nxt.x - cur.x);
            out[m].y = cur.y + t * (nxt.y - cur.y);
            m++;
        }
    }
    return m;
}

__device__ float quad_rect_iou(const F2 q1[4],
                               float x1, float y1, float x2, float y2) {
    F2 pa[8], pb[8];
#pragma unroll
    for (int i = 0; i < 4; i++) pa[i] = q1[i];
    int n = 4;
    n = clip_axis<1, +1>(pa, n, y1, pb);
    n = clip_axis<0, -1>(pb, n, x2, pa);
    n = clip_axis<1, -1>(pa, n, y2, pb);
    n = clip_axis<0, +1>(pb, n, x1, pa);

    float s = 0.f;
    for (int i = 0; i < 8; i++) {
        if (i >= n) break;
        int j = (i + 1 == n) ? 0 : i + 1;
        s += pa[i].x * pa[j].y - pa[i].y * pa[j].x;
    }
    float inter = 0.5f * fabsf(s);

    float sa1 = 0.f;
#pragma unroll
    for (int i = 0; i < 4; i++) {
        int j = (i + 1) & 3;
        sa1 += q1[i].x * q1[j].y - q1[i].y * q1[j].x;
    }
    float a1 = fabsf(0.5f * sa1);
    float a2 = (x2 - x1) * (y2 - y1);
    return inter / fmaxf(a1 + a2 - inter, 1e-8f);
}

// ================= Kernel A: lean scan + neg focal + candidate emit ========
template<int M_T, int NC_T>
__global__ void __launch_bounds__(256)
scan_kernel(const float* __restrict__ cls,
            const float* __restrict__ anch,
            const float* __restrict__ ann,
            int A, int NC_rt, int M_rt)
{
    const int M  = M_T  ? M_T  : M_rt;
    const int NC = NC_T ? NC_T : NC_rt;
    const int b  = blockIdx.y;

    __shared__ float4 s_box[MAXM];
    __shared__ float  s_a04[MAXM];
    __shared__ float  s_cls[8 * 480];
    __shared__ float  s_anch[8 * 160];

    if (blockIdx.x == 0 && threadIdx.x == 0) {
        g_bc[b] = 0.f; g_br[b] = 0.f; g_bn[b] = 0.f;
    }

    if ((threadIdx.x & 7) == 0) {
        for (int j = (threadIdx.x >> 3); j < M; j += 32) {
            const float* ar = ann + ((size_t)b * M + j) * 6;
            float a0 = ar[0], a1 = ar[1], a2 = ar[2], a3 = ar[3], a4 = ar[4], a5 = ar[5];
            float t = a4 * PI_180;
            float sa = __sinf(t) * 0.5f;
            float cb = __cosf(t) * 0.5f;
            float p0x = a0 - sa * a3 - cb * a2;
            float p0y = a1 + cb * a3 - sa * a2;
            float p1x = a0 + sa * a3 - cb * a2;
            float p1y = a1 - cb * a3 - sa * a2;
            float p2x = 2.f * a0 - p0x;
            float p2y = 2.f * a1 - p0y;
            float p3x = 2.f * a0 - p1x;
            float p3y = 2.f * a1 - p1y;
            bool valid = (a5 != -1.0f);
            float hx1 = fminf(fminf(p0x, p1x), fminf(p2x, p3x));
            float hx2 = fmaxf(fmaxf(p0x, p1x), fmaxf(p2x, p3x));
            float hy1 = fminf(fminf(p0y, p1y), fminf(p2y, p3y));
            float hy2 = fmaxf(fmaxf(p0y, p1y), fmaxf(p2y, p3y));
            if (!valid) { hx1 = hx2 = hy1 = hy2 = 1e8f; }
            s_box[j] = make_float4(hx1, hy1, hx2, hy2);
            s_a04[j] = 0.4f * (hx2 - hx1) * (hy2 - hy1);
        }
    }

    const int a    = blockIdx.x * blockDim.x + threadIdx.x;
    const int warp = threadIdx.x >> 5;
    const int lane = threadIdx.x & 31;

    {
        int a0 = (blockIdx.x * blockDim.x) + (warp << 5);
        if (a0 < A) {
            if (NC_T != 0) {
                size_t base = ((size_t)b * A + a0) * (size_t)NC;
                int maxf = (A - a0) * NC;
                if (maxf > 32 * NC) maxf = 32 * NC;
                float* dstw = s_cls + warp * 480;
                if (maxf == 32 * NC && ((base & 3) == 0)) {
                    const float4* src4 = (const float4*)(cls + base);
                    float4* dst4 = (float4*)dstw;
#pragma unroll
                    for (int i = 0; i < 4; i++) {
                        int idx = lane + i * 32;
                        if (idx < 8 * NC) dst4[idx] = src4[idx];
                    }
                } else {
                    const float* src = cls + base;
                    for (int idx = lane; idx < maxf; idx += 32) dstw[idx] = src[idx];
                }
            }
            size_t abase = (size_t)a0 * 5;
            int maxa = (A - a0) * 5;
            if (maxa > 160) maxa = 160;
            float* dsta = s_anch + warp * 160;
            if (maxa == 160 && ((abase & 3) == 0)) {
                const float4* src4 = (const float4*)(anch + abase);
                float4* dst4 = (float4*)dsta;
#pragma unroll
                for (int i = 0; i < 2; i++) {
                    int idx = lane + i * 32;
                    if (idx < 40) dst4[idx] = src4[idx];
                }
            } else {
                const float* src = anch + abase;
                for (int idx = lane; idx < maxa; idx += 32) dsta[idx] = src[idx];
            }
        }
    }
    __syncthreads();

    const float* arow = s_anch + warp * 160 + lane * 5;
    float ax1 = arow[0], ay1 = arow[1], ax2 = arow[2], ay2 = arow[3];
    float c04 = 0.4f * (ax2 - ax1) * (ay2 - ay1);

    float mx = -3.0e38f;
#pragma unroll 4
    for (int j = 0; j < M; j++) {
        float4 bb = s_box[j];
        float iw = fmaxf(fminf(ax2, bb.z) - fmaxf(ax1, bb.x), 0.f);
        float ih = fmaxf(fminf(ay2, bb.w) - fmaxf(ay1, bb.y), 0.f);
        mx = fmaxf(mx, fmaf(1.4f, iw * ih, -s_a04[j]));
    }

    bool act  = (a < A);
    bool cand = act && (mx >= c04);
    bool neg  = act && !cand;

    {
        unsigned bal = __ballot_sync(0xffffffffu, cand);
        int cw = __popc(bal);
        unsigned base = 0;
        if (lane == 0 && cw) base = atomicAdd(&g_cand_cnt, (unsigned)cw);
        base = __shfl_sync(0xffffffffu, base, 0);
        if (cand) {
            unsigned slot = base + __popc(bal & ((1u << lane) - 1u));
            if (slot < MAXCAND)
                g_cand[slot] = ((unsigned)b << 20) | (unsigned)a;
        }
    }

    float acc = 0.f;
    if (neg) {
        const float* crow = (NC_T != 0) ? (s_cls + warp * 480 + lane * NC)
                                        : (cls + ((size_t)b * A + (size_t)a) * NC);
#pragma unroll
        for (int k = 0; k < (NC_T ? NC_T : 32); k++) {
            if (NC_T == 0 && k >= NC) break;
            float p = fminf(fmaxf(crow[k], 1e-4f), 1.f - 1e-4f);
            acc = fmaf(p * p, __log2f(1.f - p), acc);
        }
    }
    float closs = acc * (-0.75f * LN2F);

#pragma unroll
    for (int o = 16; o > 0; o >>= 1)
        closs += __shfl_down_sync(0xffffffffu, closs, o);
    __shared__ float red_c[8];
    if (lane == 0) red_c[warp] = closs;
    __syncthreads();
    if (threadIdx.x == 0) {
        float tc = 0.f;
#pragma unroll
        for (int w = 0; w < 8; w++) tc += red_c[w];
        g_pc[b * gridDim.x + blockIdx.x] = tc;
    }
}

// ======= Kernel B: candidate processing + fused finalize (last block) ======
template<int M_T, int NC_T>
__global__ void __launch_bounds__(256)
cand_kernel(const float* __restrict__ cls,
            const float* __restrict__ reg,
            const float* __restrict__ anch,
            const float* __restrict__ ann,
            float* __restrict__ out,
            int A, int NC_rt, int M_rt, int B, int nblkA)
{
    const int M  = M_T  ? M_T  : M_rt;
    const int NC = NC_T ? NC_T : NC_rt;

    __shared__ float4 s_box[8][MAXM];
    __shared__ float  s_area[8][MAXM];
    __shared__ float  s_gpx[8][MAXM][4];
    __shared__ float  s_gpy[8][MAXM][4];
    __shared__ float  s_ann[8][MAXM][6];
    __shared__ float  s_ac[8], s_ar[8], s_an[8];

    if (threadIdx.x < 8) {
        s_ac[threadIdx.x] = 0.f; s_ar[threadIdx.x] = 0.f; s_an[threadIdx.x] = 0.f;
    }
    for (int t = threadIdx.x; t < B * M; t += blockDim.x) {
        int img = t / M, j = t % M;
        const float* ar = ann + ((size_t)img * M + j) * 6;
        float a0 = ar[0], a1 = ar[1], a2 = ar[2], a3 = ar[3], a4 = ar[4], a5 = ar[5];
        s_ann[img][j][0] = a0; s_ann[img][j][1] = a1; s_ann[img][j][2] = a2;
        s_ann[img][j][3] = a3; s_ann[img][j][4] = a4; s_ann[img][j][5] = a5;
        float tt = a4 * PI_180;
        float sa = __sinf(tt) * 0.5f;
        float cb = __cosf(tt) * 0.5f;
        float p0x = a0 - sa * a3 - cb * a2;
        float p0y = a1 + cb * a3 - sa * a2;
        float p1x = a0 + sa * a3 - cb * a2;
        float p1y = a1 - cb * a3 - sa * a2;
        float p2x = 2.f * a0 - p0x;
        float p2y = 2.f * a1 - p0y;
        float p3x = 2.f * a0 - p1x;
        float p3y = 2.f * a1 - p1y;
        s_gpx[img][j][0] = p0x; s_gpx[img][j][1] = p1x;
        s_gpx[img][j][2] = p2x; s_gpx[img][j][3] = p3x;
        s_gpy[img][j][0] = p0y; s_gpy[img][j][1] = p1y;
        s_gpy[img][j][2] = p2y; s_gpy[img][j][3] = p3y;
        bool valid = (a5 != -1.0f);
        float hx1 = fminf(fminf(p0x, p1x), fminf(p2x, p3x));
        float hx2 = fmaxf(fmaxf(p0x, p1x), fmaxf(p2x, p3x));
        float hy1 = fminf(fminf(p0y, p1y), fminf(p2y, p3y));
        float hy2 = fmaxf(fmaxf(p0y, p1y), fmaxf(p2y, p3y));
        if (!valid) { hx1 = hx2 = hy1 = hy2 = 1e8f; }
        s_box[img][j]  = make_float4(hx1, hy1, hx2, hy2);
        s_area[img][j] = (hx2 - hx1) * (hy2 - hy1);
    }
    __syncthreads();

    unsigned cnt = g_cand_cnt;
    if (cnt > MAXCAND) cnt = MAXCAND;

    for (unsigned i = blockIdx.x * blockDim.x + threadIdx.x; i < cnt;
         i += gridDim.x * blockDim.x) {
        unsigned u = g_cand[i];
        int b = (int)(u >> 20);
        int a = (int)(u & 0xFFFFFu);

        const float* arow = anch + (size_t)a * 5;
        float ax1 = arow[0], ay1 = arow[1], ax2 = arow[2], ay2 = arow[3], ath = arow[4];
        float aw = ax2 - ax1, ah = ay2 - ay1;
        float aArea = aw * ah;

        float cbi = -1.f, cbu = 1.f;
        int hg = 0;
#pragma unroll 8
        for (int j = 0; j < M; j++) {
            float4 bb = s_box[b][j];
            float iw = fmaxf(fminf(ax2, bb.z) - fmaxf(ax1, bb.x), 0.f);
            float ih = fmaxf(fminf(ay2, bb.w) - fmaxf(ay1, bb.y), 0.f);
            float inter = iw * ih;
            float ua = aArea + s_area[b][j] - inter;
            if (inter * cbu > cbi * ua) { cbi = inter; cbu = ua; hg = j; }
        }

        bool pos = false;
        if (cbi >= 0.6f * cbu) {
            F2 q1[4];
#pragma unroll
            for (int c = 0; c < 4; c++) {
                q1[c].x = s_gpx[b][hg][c];
                q1[c].y = s_gpy[b][hg][c];
            }
            pos = (quad_rect_iou(q1, ax1, ay1, ax2, ay2) >= 0.3f);
        }

        if (pos) {
            float acc = 0.f;
            const float* crow = cls + ((size_t)b * A + (size_t)a) * NC;
            int tc = (int)s_ann[b][hg][5];
#pragma unroll
            for (int k = 0; k < (NC_T ? NC_T : 32); k++) {
                if (NC_T == 0 && k >= NC) break;
                float p = fminf(fmaxf(crow[k], 1e-4f), 1.f - 1e-4f);
                if (k == tc) {
                    float q = 1.f - p;
                    acc = fmaf((1.f / 3.f) * q * q, __log2f(p), acc);
                } else {
                    acc = fmaf(p * p, __log2f(1.f - p), acc);
                }
            }
            float closs = acc * (-0.75f * LN2F);

            float acx = ax1 + 0.5f * aw;
            float acy = ay1 + 0.5f * ah;
            float gw = fmaxf(s_ann[b][hg][2], 1.f);
            float gh = fmaxf(s_ann[b][hg][3], 1.f);
            float t5[5];
            t5[0] = ((s_ann[b][hg][0] - acx) / aw) * 10.f;
            t5[1] = ((s_ann[b][hg][1] - acy) / ah) * 10.f;
            t5[2] = __logf(gw / aw) * 5.f;
            t5[3] = __logf(gh / ah) * 5.f;
            t5[4] = ((s_ann[b][hg][4] - ath) * PI_180) * 10.f;
            const float* rrow = reg + ((size_t)b * A + (size_t)a) * 5;
            float rsum = 0.f;
#pragma unroll
            for (int k = 0; k < 5; k++) {
                float d = fabsf(t5[k] - rrow[k]);
                rsum += (d <= (1.f / 9.f)) ? 4.5f * d * d : (d - (0.5f / 9.f));
            }

            atomicAdd(&s_ac[b], closs);
            atomicAdd(&s_ar[b], rsum);
            atomicAdd(&s_an[b], 1.f);
        }
    }
    __syncthreads();
    if (threadIdx.x < 8) {
        int t = threadIdx.x;
        if (s_an[t] != 0.f || s_ac[t] != 0.f) {
            atomicAdd(&g_bc[t], s_ac[t]);
            atomicAdd(&g_br[t], s_ar[t]);
            atomicAdd(&g_bn[t], s_an[t]);
        }
    }

    // ---- fused finalize: last block ----
    __shared__ unsigned s_isLast;
    if (threadIdx.x == 0) {
        __threadfence();
        unsigned old = atomicAdd(&g_done2, 1u);
        s_isLast = (old == gridDim.x - 1u) ? 1u : 0u;
    }
    __syncthreads();
    if (s_isLast) {
        int w = threadIdx.x >> 5;
        int lane = threadIdx.x & 31;
        __shared__ float s_c[8], s_r[8];
        if (w < B) {
            float tc = 0.f;
            for (int i = lane; i < nblkA; i += 32)
                tc += __ldcg(&g_pc[w * nblkA + i]);
#pragma unroll
            for (int o = 16; o > 0; o >>= 1)
                tc += __shfl_down_sync(0xffffffffu, tc, o);
            if (lane == 0) {
                float np = __ldcg(&g_bn[w]);
                float cl = tc + __ldcg(&g_bc[w]);
                s_c[w] = cl / fmaxf(np, 1.f);
                s_r[w] = (np > 0.f) ? (__ldcg(&g_br[w]) / fmaxf(np * 5.f, 1.f)) : 0.f;
            }
        }
        __syncthreads();
        if (threadIdx.x == 0) {
            float cm = 0.f, rm = 0.f;
            for (int bb = 0; bb < B; bb++) { cm += s_c[bb]; rm += s_r[bb]; }
            out[0] = cm / (float)B;
            out[1] = rm / (float)B;
            g_cand_cnt = 0;   // reset for next graph replay
            g_done2 = 0;
        }
    }
}

extern "C" void kernel_launch(void* const* d_in, const int* in_sizes, int n_in,
                              void* d_out, int out_size) {
    const float* cls  = (const float*)d_in[0];
    const float* reg  = (const float*)d_in[1];
    const float* anch = (const float*)d_in[2];
    const float* ann  = (const float*)d_in[3];
    float* out = (float*)d_out;

    int A  = in_sizes[2] / 5;
    int B  = in_sizes[1] / (A * 5);
    int NC = in_sizes[0] / (B * A);
    int M  = in_sizes[3] / (B * 6);
    if (M > MAXM) M = MAXM;
    int Bc = (B > 8) ? 8 : B;

    int nblk = (A + 255) / 256;
    dim3 gridA(nblk, Bc);
    if (M == 32 && NC == 15) {
        scan_kernel<32, 15><<<gridA, 256>>>(cls, anch, ann, A, NC, M);
        cand_kernel<32, 15><<<296, 256>>>(cls, reg, anch, ann, out, A, NC, M, Bc, nblk);
    } else {
        scan_kernel<0, 0><<<gridA, 256>>>(cls, anch, ann, A, NC, M);
        cand_kernel<0, 0><<<296, 256>>>(cls, reg, anch, ann, out, A, NC, M, Bc, nblk);
    }
}